// round 4
// baseline (speedup 1.0000x reference)
#include <cuda_runtime.h>
#include <cstdint>
#include <cstddef>

// Problem constants
#define NU      100
#define TSTEPS  60
#define BTOT    8192
// derived output offsets (all float32, concatenated in reference tuple order)
static const size_t OFFU  = 0;         // u:        (B,60,7)
static const size_t OFFT  = 3440640;   // target:   (B,60)
static const size_t OFFRS = 3932160;   // respmask: (B,60)
static const size_t OFFL  = 4423680;   // licked:   (B,)
static const size_t OFFR  = 4431872;   // reward:   (B,)
static const size_t OFFZ  = 4440064;   // z_seq:    (B,60)
static const size_t OFFYF = 4931584;   // yf:       (B,100)

// noise_scale = 0.15 * sqrt(2*0.2)
#define NSCALE 0.09486832980505138f

// ---- packed f32x2 helpers (Blackwell FFMA2) ----
__device__ __forceinline__ unsigned long long dup2(float x){
    unsigned long long r;
    asm("mov.b64 %0, {%1, %1};" : "=l"(r) : "f"(x));
    return r;
}
__device__ __forceinline__ void fma2(unsigned long long &a, unsigned long long x, unsigned long long y){
    asm("fma.rn.f32x2 %0, %1, %2, %0;" : "+l"(a) : "l"(x), "l"(y));
}
__device__ __forceinline__ float2 unpk(unsigned long long v){
    float lo, hi;
    asm("mov.b64 {%0, %1}, %2;" : "=f"(lo), "=f"(hi) : "l"(v));
    return make_float2(lo, hi);
}

// float4 component by (compile-time-unrolled) index
#define NZC(s,u) ((u)==0 ? nz[s].x : (u)==1 ? nz[s].y : (u)==2 ? nz[s].z : nz[s].w)

// Row permutation: source unit j lives at shared row pi(j) = 32*(j%4) + (j/4).
// Lane l publishes its unit (4l+u) at row 32u+l  => lane stride = 68 floats
// = 4 (mod 32) banks => 4-way conflict instead of 16-way with the old layout.
#define YSTRIDE 68

// Shared layout (floats): WtP[128 rows][128] | Ysh[121 rows][68] | WinS[7][128]
#define SM_WT   0
#define SM_Y    16384
#define SM_WIN  (16384 + 121*YSTRIDE)
#define SM_FLOATS (16384 + 121*YSTRIDE + 7*128)

__global__ __launch_bounds__(256, 1)
void rnn_dynrouting_kernel(
    const float* __restrict__ y0,      const float* __restrict__ noise,
    const int*   __restrict__ stimI,   const int*   __restrict__ rewI,
    const int*   __restrict__ instrI,
    const float* __restrict__ WinRaw,  const float* __restrict__ Wrec,
    const float* __restrict__ brec,    const float* __restrict__ wout,
    const float* __restrict__ bout,
    float* __restrict__ out)
{
    extern __shared__ float sm[];
    float* WtP  = sm + SM_WT;    // WtP[r*128 + i] = Wrec[i][4*(r&31) + (r>>5)], zero-padded
    float* Ysh  = sm + SM_Y;     // Ysh[r*68 + trialcol], r = permuted source-unit row
    float* WinS = sm + SM_WIN;   // WinS[k*128 + i] = |W_in_raw[i][k]|, zero-padded

    const int tid = threadIdx.x;

    // ---- one-time shared init (single pass, race-free) ----
    for (int idx = tid; idx < 128*128; idx += 256) {
        int r = idx >> 7, i = idx & 127;
        int u = r >> 5,  l = r & 31;         // source unit j = 4l + u
        float v = 0.0f;
        if (i < NU && l < 25) v = Wrec[i*NU + 4*l + u];
        WtP[idx] = v;
    }
    for (int idx = tid; idx < 7*128; idx += 256) {
        int k = idx >> 7, i = idx & 127;
        WinS[idx] = (i < NU) ? fabsf(WinRaw[i*7 + k]) : 0.0f;
    }
    __syncthreads();

    const int lane = tid & 31;
    const int warp = tid >> 5;
    const int tb   = blockIdx.x * 64 + warp * 8;    // first trial of this warp's octet
    const int i0   = 4 * lane;                       // first unit of this lane (blocked)
    const bool act = (i0 < NU);                      // lane < 25

    // per-lane constant weights for its 4 units
    float w4[4], w5[4], w6[4], wo[4];
    unsigned long long bd[4];
    #pragma unroll
    for (int u = 0; u < 4; u++) {
        int i = i0 + u;
        w4[u] = WinS[4*128 + i];   // w_reward
        w5[u] = WinS[5*128 + i];   // w_lick
        w6[u] = WinS[6*128 + i];   // response-input column
        wo[u] = (i < NU) ? wout[i] : 0.0f;
        bd[u] = dup2((i < NU) ? brec[i] : 0.0f);
    }
    const float b0 = bout[0];

    // per-trial constants, replicated in every lane (bit-packed)
    unsigned isRewM = 0, instrBM = 0, stimP = 0;
    #pragma unroll
    for (int s = 0; s < 8; s++) {
        int b = tb + s;
        int sv = stimI[b];
        stimP  |= (unsigned)(sv & 3) << (2*s);
        isRewM |= (unsigned)(sv == rewI[b]) << s;
        instrBM|= (unsigned)(instrI[b] > 0) << s;
    }

    // per-trial state (replicated)
    unsigned lickedM = 0, instrFiredM = 0;
    int lickT[8];
    #pragma unroll
    for (int s = 0; s < 8; s++) lickT[s] = TSTEPS + 1;

    // y state: y[u][s], init from y0
    float y[4][8];
    #pragma unroll
    for (int s = 0; s < 8; s++) {
        if (act) {
            float4 v = *reinterpret_cast<const float4*>(y0 + (size_t)(tb + s)*NU + i0);
            y[0][s] = v.x; y[1][s] = v.y; y[2][s] = v.z; y[3][s] = v.w;
        } else {
            y[0][s] = 0.f; y[1][s] = 0.f; y[2][s] = 0.f; y[3][s] = 0.f;
        }
    }
    // write initial y into this warp's private columns of Ysh (permuted rows)
    if (act) {
        #pragma unroll
        for (int u = 0; u < 4; u++) {
            float* row = Ysh + (size_t)(32*u + lane)*YSTRIDE + 8*warp;
            *reinterpret_cast<float4*>(row)     = make_float4(y[u][0], y[u][1], y[u][2], y[u][3]);
            *reinterpret_cast<float4*>(row + 4) = make_float4(y[u][4], y[u][5], y[u][6], y[u][7]);
        }
    }
    __syncwarp();

    float4 nz[8];
    #pragma unroll
    for (int s = 0; s < 8; s++) nz[s] = make_float4(0.f, 0.f, 0.f, 0.f);

    const float* wp = WtP + i0;
    const float* yp = Ysh + 8*warp;

    // ==================== time loop ====================
    for (int t = 0; t < TSTEPS; t++) {
        const bool inResp = (t >= 20) && (t < 35);
        const bool inStim = (t >= 10) && (t < 15);

        // ---- per-trial coefficients (all lanes replicate; no comms needed) ----
        float cA[8], cB[8];
        unsigned instrActM = 0;
        #pragma unroll
        for (int s = 0; s < 8; s++) {
            bool lic = (lickedM >> s) & 1;
            bool ifd = (instrFiredM >> s) & 1;
            bool irw = (isRewM >> s) & 1;
            bool ib  = (instrBM >> s) & 1;
            bool delivered = ifd || (lic && irw);
            if (ib && !delivered && (t == 30)) instrFiredM |= 1u << s;
            bool instrAct = ((instrFiredM >> s) & 1) && (t >= 30) && (t < 35);
            if (instrAct) instrActM |= 1u << s;
            bool lickDyn = lic && (t > lickT[s]) && (t < lickT[s] + 5);
            cA[s] = (instrAct ? 1.0f : 0.0f) + ((lickDyn && irw) ? 1.0f : 0.0f);
            cB[s] = lickDyn ? 1.0f : 0.0f;
        }

        // ---- prefetch this step's noise (hidden under the matvec) ----
        if (act) {
            #pragma unroll
            for (int s = 0; s < 8; s++) {
                nz[s] = __ldg(reinterpret_cast<const float4*>(
                          noise + (size_t)(tb + s)*(TSTEPS*NU) + (size_t)t*NU + i0));
            }
        }

        // ---- matvec over permuted rows r = 32u + l, l in [0,25) ----
        unsigned long long acc[4][4];
        #pragma unroll
        for (int u = 0; u < 4; u++) {
            acc[u][0] = bd[u]; acc[u][1] = bd[u]; acc[u][2] = bd[u]; acc[u][3] = bd[u];
        }
        #pragma unroll
        for (int ur = 0; ur < 4; ur++) {
            const float* wr = wp + (size_t)(32*ur)*128;
            const float* yr = yp + (size_t)(32*ur)*YSTRIDE;
            #pragma unroll 5
            for (int l = 0; l < 25; l++) {
                float4 w = *reinterpret_cast<const float4*>(wr + l*128);
                ulonglong2 ya = *reinterpret_cast<const ulonglong2*>(yr + l*YSTRIDE);
                ulonglong2 yb = *reinterpret_cast<const ulonglong2*>(yr + l*YSTRIDE + 4);
                unsigned long long w0 = dup2(w.x), w1 = dup2(w.y), w2 = dup2(w.z), w3 = dup2(w.w);
                fma2(acc[0][0], w0, ya.x); fma2(acc[0][1], w0, ya.y); fma2(acc[0][2], w0, yb.x); fma2(acc[0][3], w0, yb.y);
                fma2(acc[1][0], w1, ya.x); fma2(acc[1][1], w1, ya.y); fma2(acc[1][2], w1, yb.x); fma2(acc[1][3], w1, yb.y);
                fma2(acc[2][0], w2, ya.x); fma2(acc[2][1], w2, ya.y); fma2(acc[2][2], w2, yb.x); fma2(acc[2][3], w2, yb.y);
                fma2(acc[3][0], w3, ya.x); fma2(acc[3][1], w3, ya.y); fma2(acc[3][2], w3, yb.x); fma2(acc[3][3], w3, yb.y);
            }
        }

        // ---- epilogue: pre -> relu -> leaky update ----
        float pre[4][8];
        #pragma unroll
        for (int u = 0; u < 4; u++) {
            #pragma unroll
            for (int p = 0; p < 4; p++) {
                float2 v = unpk(acc[u][p]);
                pre[u][2*p] = v.x; pre[u][2*p+1] = v.y;
            }
        }
        if (inStim) {
            #pragma unroll
            for (int s = 0; s < 8; s++) {
                int sv = (stimP >> (2*s)) & 3;
                float4 wv = *reinterpret_cast<const float4*>(WinS + sv*128 + i0);
                pre[0][s] += wv.x; pre[1][s] += wv.y; pre[2][s] += wv.z; pre[3][s] += wv.w;
            }
        }
        const float a6 = inResp ? 1.0f : 0.0f;
        const bool doAdd = (t >= 20);   // cA/cB can only be nonzero from t>=21/30
        #pragma unroll
        for (int u = 0; u < 4; u++) {
            #pragma unroll
            for (int s = 0; s < 8; s++) {
                float p = fmaf(a6, w6[u], pre[u][s]);
                if (doAdd) p = fmaf(cA[s], w4[u], fmaf(cB[s], w5[u], p));
                p = fmaf(NSCALE, NZC(s, u), p);
                float r = fmaxf(p, 0.0f);
                y[u][s] = 0.8f * y[u][s] + 0.2f * r;
            }
        }

        // ---- publish y for next step's matvec (permuted rows, 4-way max conflict) ----
        __syncwarp();   // all lanes done reading Ysh before anyone overwrites
        if (act) {
            #pragma unroll
            for (int u = 0; u < 4; u++) {
                float* row = Ysh + (size_t)(32*u + lane)*YSTRIDE + 8*warp;
                *reinterpret_cast<float4*>(row)     = make_float4(y[u][0], y[u][1], y[u][2], y[u][3]);
                *reinterpret_cast<float4*>(row + 4) = make_float4(y[u][4], y[u][5], y[u][6], y[u][7]);
            }
        }

        // ---- readout: logit[s] = y . w_out + b0 via shuffle butterfly ----
        float part[8];
        #pragma unroll
        for (int s = 0; s < 8; s++) {
            part[s] = fmaf(y[0][s], wo[0],
                      fmaf(y[1][s], wo[1],
                      fmaf(y[2][s], wo[2], y[3][s] * wo[3])));
        }
        #pragma unroll
        for (int off = 16; off > 0; off >>= 1) {
            #pragma unroll
            for (int s = 0; s < 8; s++)
                part[s] += __shfl_xor_sync(0xffffffffu, part[s], off);
        }

        // ---- lick state machine + per-step outputs ----
        unsigned u5M = 0, u4M = 0;
        #pragma unroll
        for (int s = 0; s < 8; s++) {
            float lg = part[s] + b0;
            bool lic = (lickedM >> s) & 1;
            bool trig = inResp && !lic && (lg > 0.0f);   // sigmoid(x)>0.5 <=> x>0
            if (trig) { lickT[s] = t; lickedM |= 1u << s; }
            bool lic2 = (lickedM >> s) & 1;
            bool u5 = lic2 && (t >= lickT[s]) && (t < lickT[s] + 5);
            bool u4 = ((instrActM >> s) & 1) || (u5 && ((isRewM >> s) & 1));
            if (u5) u5M |= 1u << s;
            if (u4) u4M |= 1u << s;
        }
        // lane s writes trial s's z, u[...,4], u[...,5]
        float myPart = part[0];
        #pragma unroll
        for (int s = 1; s < 8; s++) if ((lane & 7) == s) myPart = part[s];
        if (lane < 8) {
            int s = lane;
            float lg = myPart + b0;
            out[OFFZ + (size_t)(tb + s)*TSTEPS + t] = 1.0f / (1.0f + __expf(-lg));
            size_t ub = OFFU + (size_t)(tb + s)*(TSTEPS*7) + (size_t)t*7;
            out[ub + 4] = ((u4M >> s) & 1) ? 1.0f : 0.0f;
            out[ub + 5] = ((u5M >> s) & 1) ? 1.0f : 0.0f;
        }
        __syncwarp();   // y writes visible before next step's matvec reads
    }

    // ==================== final outputs ====================
    // yf
    if (act) {
        #pragma unroll
        for (int s = 0; s < 8; s++) {
            *reinterpret_cast<float4*>(out + OFFYF + (size_t)(tb + s)*NU + i0) =
                make_float4(y[0][s], y[1][s], y[2][s], y[3][s]);
        }
    }
    // licked / reward_delivered
    if (lane < 8) {
        int s = lane;
        bool lic = (lickedM >> s) & 1;
        bool irw = (isRewM >> s) & 1;
        bool ifd = (instrFiredM >> s) & 1;
        out[OFFL + (size_t)(tb + s)] = lic ? 1.0f : 0.0f;
        out[OFFR + (size_t)(tb + s)] = (ifd || (lic && irw)) ? 1.0f : 0.0f;
    }
    // static per-(trial,t) outputs: u cols 0..3 & 6, target, resp_mask
    for (int idx = lane; idx < 8*TSTEPS; idx += 32) {
        int s = idx / TSTEPS;
        int t = idx - s*TSTEPS;
        size_t b = (size_t)(tb + s);
        bool resp = (t >= 20) && (t < 35);
        bool stm  = (t >= 10) && (t < 15);
        int sv = (stimP >> (2*s)) & 3;
        bool irw = (isRewM >> s) & 1;
        float* ub = out + OFFU + b*(TSTEPS*7) + (size_t)t*7;
        ub[0] = (stm && sv == 0) ? 1.0f : 0.0f;
        ub[1] = (stm && sv == 1) ? 1.0f : 0.0f;
        ub[2] = (stm && sv == 2) ? 1.0f : 0.0f;
        ub[3] = (stm && sv == 3) ? 1.0f : 0.0f;
        ub[6] = resp ? 1.0f : 0.0f;
        out[OFFT  + b*TSTEPS + t] = (irw && resp) ? 1.0f : 0.0f;
        out[OFFRS + b*TSTEPS + t] = resp ? 1.0f : 0.0f;
    }
}

extern "C" void kernel_launch(void* const* d_in, const int* in_sizes, int n_in,
                              void* d_out, int out_size) {
    const float* y0     = (const float*)d_in[0];
    const float* noise  = (const float*)d_in[1];
    const int*   stim   = (const int*)  d_in[2];
    const int*   rew    = (const int*)  d_in[3];
    const int*   instr  = (const int*)  d_in[4];
    const float* WinRaw = (const float*)d_in[5];
    const float* Wrec   = (const float*)d_in[6];
    const float* brec   = (const float*)d_in[7];
    const float* wout   = (const float*)d_in[8];
    const float* bout   = (const float*)d_in[9];
    float* out = (float*)d_out;

    const int smem_bytes = SM_FLOATS * (int)sizeof(float);  // ~102 KB
    cudaFuncSetAttribute(rnn_dynrouting_kernel,
                         cudaFuncAttributeMaxDynamicSharedMemorySize, smem_bytes);
    rnn_dynrouting_kernel<<<BTOT/64, 256, smem_bytes>>>(
        y0, noise, stim, rew, instr, WinRaw, Wrec, brec, wout, bout, out);
}

// round 5
// speedup vs baseline: 1.0794x; 1.0794x over previous
#include <cuda_runtime.h>
#include <cstdint>
#include <cstddef>

// Problem constants
#define NU      100
#define TSTEPS  60
#define BTOT    8192
// derived output offsets (all float32, concatenated in reference tuple order)
static const size_t OFFU  = 0;         // u:        (B,60,7)
static const size_t OFFT  = 3440640;   // target:   (B,60)
static const size_t OFFRS = 3932160;   // respmask: (B,60)
static const size_t OFFL  = 4423680;   // licked:   (B,)
static const size_t OFFR  = 4431872;   // reward:   (B,)
static const size_t OFFZ  = 4440064;   // z_seq:    (B,60)
static const size_t OFFYF = 4931584;   // yf:       (B,100)

// noise_scale = 0.15 * sqrt(2*0.2)
#define NSCALE 0.09486832980505138f

// 4 trials per warp, 8 warps (256 thr) per block, 32 trials/block, grid 256.
#define TPW 4
#define TPB 32

// ---- packed f32x2 helpers (Blackwell FFMA2) ----
__device__ __forceinline__ unsigned long long dup2(float x){
    unsigned long long r;
    asm("mov.b64 %0, {%1, %1};" : "=l"(r) : "f"(x));
    return r;
}
__device__ __forceinline__ void fma2(unsigned long long &a, unsigned long long x, unsigned long long y){
    asm("fma.rn.f32x2 %0, %1, %2, %0;" : "+l"(a) : "l"(x), "l"(y));
}
__device__ __forceinline__ float2 unpk(unsigned long long v){
    float lo, hi;
    asm("mov.b64 {%0, %1}, %2;" : "=f"(lo), "=f"(hi) : "l"(v));
    return make_float2(lo, hi);
}

// Shared layout (floats):
//   Wpk[100][128] : Wpk[j*128 + 4*l + u] = Wrec[(32u+l)][j]  (0 if unit >= 100)
//   Ysh [100][36] : Ysh[j*36 + col], col = 4*warp + s   (trial column)
//   WinS[7][128]  : WinS[k*128 + i] = |W_in_raw[i][k]|   (0 pad)
#define YS 36
#define SM_W   0
#define SM_Y   12800
#define SM_WIN (12800 + 100*YS)
#define SM_FLOATS (12800 + 100*YS + 7*128)

__global__ __launch_bounds__(256, 2)
void rnn_dynrouting_kernel(
    const float* __restrict__ y0,      const float* __restrict__ noise,
    const int*   __restrict__ stimI,   const int*   __restrict__ rewI,
    const int*   __restrict__ instrI,
    const float* __restrict__ WinRaw,  const float* __restrict__ Wrec,
    const float* __restrict__ brec,    const float* __restrict__ wout,
    const float* __restrict__ bout,
    float* __restrict__ out)
{
    extern __shared__ float sm[];
    float* Wpk  = sm + SM_W;
    float* Ysh  = sm + SM_Y;
    float* WinS = sm + SM_WIN;

    const int tid = threadIdx.x;

    // ---- one-time shared init ----
    for (int idx = tid; idx < 100*128; idx += 256) {
        int j = idx >> 7, c = idx & 127;
        int l = c >> 2, u = c & 3;            // packed lane-major: c = 4l+u
        int i = 32*u + l;                     // unit id
        Wpk[idx] = (i < NU) ? Wrec[i*NU + j] : 0.0f;
    }
    for (int idx = tid; idx < 7*128; idx += 256) {
        int k = idx >> 7, i = idx & 127;
        WinS[idx] = (i < NU) ? fabsf(WinRaw[i*7 + k]) : 0.0f;
    }
    __syncthreads();

    const int lane = tid & 31;
    const int warp = tid >> 5;
    const int tb   = blockIdx.x * TPB + warp * TPW;  // first trial of this warp
    // interleaved unit ownership: unit(u) = 32u + lane
    const bool v3  = (lane < 4);                     // u==3 validity; u<3 always valid

    // per-lane constants
    float wo[4], bdf[4];
    #pragma unroll
    for (int u = 0; u < 4; u++) {
        int i = 32*u + lane;
        bool v = (u < 3) || v3;
        wo[u]  = v ? wout[i] : 0.0f;
        bdf[u] = v ? brec[i] : 0.0f;
    }
    const float b0 = bout[0];

    // per-trial constants, replicated in every lane (bit-packed)
    unsigned isRewM = 0, instrBM = 0, stimP = 0;
    #pragma unroll
    for (int s = 0; s < TPW; s++) {
        int b = tb + s;
        int sv = stimI[b];
        stimP  |= (unsigned)(sv & 3) << (2*s);
        isRewM |= (unsigned)(sv == rewI[b]) << s;
        instrBM|= (unsigned)(instrI[b] > 0) << s;
    }

    // per-trial state (replicated)
    unsigned lickedM = 0, instrFiredM = 0;
    int lickT[TPW];
    #pragma unroll
    for (int s = 0; s < TPW; s++) lickT[s] = TSTEPS + 1;

    // y state: y[u][s]
    float y[4][TPW];
    #pragma unroll
    for (int u = 0; u < 4; u++) {
        bool v = (u < 3) || v3;
        #pragma unroll
        for (int s = 0; s < TPW; s++)
            y[u][s] = v ? y0[(size_t)(tb + s)*NU + 32*u + lane] : 0.0f;
    }
    // publish initial y (conflict-free: lane stride = 1 row = 36 floats = 4 banks)
    #pragma unroll
    for (int u = 0; u < 4; u++) {
        if (u < 3 || v3) {
            float* row = Ysh + (size_t)(32*u + lane)*YS + TPW*warp;
            *reinterpret_cast<float4*>(row) = make_float4(y[u][0], y[u][1], y[u][2], y[u][3]);
        }
    }
    __syncwarp();

    const float* wp = Wpk + 4*lane;
    const float* yp = Ysh + TPW*warp;

    float nz[4][TPW];
    #pragma unroll
    for (int u = 0; u < 4; u++)
        #pragma unroll
        for (int s = 0; s < TPW; s++) nz[u][s] = 0.0f;

    // ==================== time loop ====================
    for (int t = 0; t < TSTEPS; t++) {
        const bool inResp = (t >= 20) && (t < 35);
        const bool inStim = (t >= 10) && (t < 15);

        // ---- per-trial coefficients (all lanes replicate) ----
        float cA[TPW], cB[TPW];
        unsigned instrActM = 0;
        #pragma unroll
        for (int s = 0; s < TPW; s++) {
            bool lic = (lickedM >> s) & 1;
            bool ifd = (instrFiredM >> s) & 1;
            bool irw = (isRewM >> s) & 1;
            bool ib  = (instrBM >> s) & 1;
            bool delivered = ifd || (lic && irw);
            if (ib && !delivered && (t == 30)) instrFiredM |= 1u << s;
            bool instrAct = ((instrFiredM >> s) & 1) && (t >= 30) && (t < 35);
            if (instrAct) instrActM |= 1u << s;
            bool lickDyn = lic && (t > lickT[s]) && (t < lickT[s] + 5);
            cA[s] = (instrAct ? 1.0f : 0.0f) + ((lickDyn && irw) ? 1.0f : 0.0f);
            cB[s] = lickDyn ? 1.0f : 0.0f;
        }

        // ---- prefetch this step's noise (coalesced scalars; hidden under matvec) ----
        #pragma unroll
        for (int u = 0; u < 4; u++) {
            if (u < 3 || v3) {
                #pragma unroll
                for (int s = 0; s < TPW; s++)
                    nz[u][s] = __ldg(noise + (size_t)(tb + s)*(TSTEPS*NU) + (size_t)t*NU + 32*u + lane);
            }
        }

        // ---- matvec: acc[u][p] = b_rec + sum_j W[i][j]*y[j]  (f32x2 over trial pairs) ----
        unsigned long long acc[4][2];
        #pragma unroll
        for (int u = 0; u < 4; u++) {
            unsigned long long b = dup2(bdf[u]);
            acc[u][0] = b; acc[u][1] = b;
        }
        #pragma unroll 10
        for (int j = 0; j < NU; j++) {
            float4 w = *reinterpret_cast<const float4*>(wp + j*128);      // W for this lane's 4 units
            ulonglong2 ya = *reinterpret_cast<const ulonglong2*>(yp + j*YS); // y[j] for 4 trials (broadcast)
            unsigned long long w0 = dup2(w.x), w1 = dup2(w.y), w2 = dup2(w.z), w3 = dup2(w.w);
            fma2(acc[0][0], w0, ya.x); fma2(acc[0][1], w0, ya.y);
            fma2(acc[1][0], w1, ya.x); fma2(acc[1][1], w1, ya.y);
            fma2(acc[2][0], w2, ya.x); fma2(acc[2][1], w2, ya.y);
            fma2(acc[3][0], w3, ya.x); fma2(acc[3][1], w3, ya.y);
        }

        // ---- epilogue: pre -> relu -> leaky update ----
        float pre[4][TPW];
        #pragma unroll
        for (int u = 0; u < 4; u++) {
            float2 a = unpk(acc[u][0]), b = unpk(acc[u][1]);
            pre[u][0] = a.x; pre[u][1] = a.y; pre[u][2] = b.x; pre[u][3] = b.y;
        }
        if (inStim) {
            #pragma unroll
            for (int s = 0; s < TPW; s++) {
                int sv = (stimP >> (2*s)) & 3;
                #pragma unroll
                for (int u = 0; u < 4; u++)
                    pre[u][s] += WinS[sv*128 + 32*u + lane];
            }
        }
        const float a6 = inResp ? 1.0f : 0.0f;
        const bool doAdd = (t >= 20);   // cA/cB only nonzero from t>=21/30
        #pragma unroll
        for (int u = 0; u < 4; u++) {
            const int iu = 32*u + lane;
            const float w6u = WinS[6*128 + iu];
            const float w4u = WinS[4*128 + iu];
            const float w5u = WinS[5*128 + iu];
            #pragma unroll
            for (int s = 0; s < TPW; s++) {
                float p = fmaf(a6, w6u, pre[u][s]);
                if (doAdd) p = fmaf(cA[s], w4u, fmaf(cB[s], w5u, p));
                p = fmaf(NSCALE, nz[u][s], p);
                float r = fmaxf(p, 0.0f);
                y[u][s] = 0.8f * y[u][s] + 0.2f * r;
            }
        }

        // ---- publish y (conflict-free) ----
        __syncwarp();   // all lanes done reading Ysh before overwrite
        #pragma unroll
        for (int u = 0; u < 4; u++) {
            if (u < 3 || v3) {
                float* row = Ysh + (size_t)(32*u + lane)*YS + TPW*warp;
                *reinterpret_cast<float4*>(row) = make_float4(y[u][0], y[u][1], y[u][2], y[u][3]);
            }
        }

        // ---- readout: logit[s] = y . w_out + b0 via shuffle butterfly ----
        float part[TPW];
        #pragma unroll
        for (int s = 0; s < TPW; s++) {
            part[s] = fmaf(y[0][s], wo[0],
                      fmaf(y[1][s], wo[1],
                      fmaf(y[2][s], wo[2], y[3][s] * wo[3])));
        }
        #pragma unroll
        for (int off = 16; off > 0; off >>= 1) {
            #pragma unroll
            for (int s = 0; s < TPW; s++)
                part[s] += __shfl_xor_sync(0xffffffffu, part[s], off);
        }

        // ---- lick state machine + per-step outputs ----
        unsigned u5M = 0, u4M = 0;
        #pragma unroll
        for (int s = 0; s < TPW; s++) {
            float lg = part[s] + b0;
            bool lic = (lickedM >> s) & 1;
            bool trig = inResp && !lic && (lg > 0.0f);   // sigmoid(x)>0.5 <=> x>0
            if (trig) { lickT[s] = t; lickedM |= 1u << s; }
            bool lic2 = (lickedM >> s) & 1;
            bool u5 = lic2 && (t >= lickT[s]) && (t < lickT[s] + 5);
            bool u4 = ((instrActM >> s) & 1) || (u5 && ((isRewM >> s) & 1));
            if (u5) u5M |= 1u << s;
            if (u4) u4M |= 1u << s;
        }
        // lane s (<4) writes trial s's z, u[...,4], u[...,5]
        float myPart = part[0];
        #pragma unroll
        for (int s = 1; s < TPW; s++) if ((lane & 3) == s) myPart = part[s];
        if (lane < TPW) {
            int s = lane;
            float lg = myPart + b0;
            out[OFFZ + (size_t)(tb + s)*TSTEPS + t] = 1.0f / (1.0f + __expf(-lg));
            size_t ub = OFFU + (size_t)(tb + s)*(TSTEPS*7) + (size_t)t*7;
            out[ub + 4] = ((u4M >> s) & 1) ? 1.0f : 0.0f;
            out[ub + 5] = ((u5M >> s) & 1) ? 1.0f : 0.0f;
        }
        __syncwarp();   // y writes visible before next step's matvec reads
    }

    // ==================== final outputs ====================
    // yf (coalesced scalar stores)
    #pragma unroll
    for (int u = 0; u < 4; u++) {
        if (u < 3 || v3) {
            #pragma unroll
            for (int s = 0; s < TPW; s++)
                out[OFFYF + (size_t)(tb + s)*NU + 32*u + lane] = y[u][s];
        }
    }
    // licked / reward_delivered
    if (lane < TPW) {
        int s = lane;
        bool lic = (lickedM >> s) & 1;
        bool irw = (isRewM >> s) & 1;
        bool ifd = (instrFiredM >> s) & 1;
        out[OFFL + (size_t)(tb + s)] = lic ? 1.0f : 0.0f;
        out[OFFR + (size_t)(tb + s)] = (ifd || (lic && irw)) ? 1.0f : 0.0f;
    }
    // static per-(trial,t) outputs: u cols 0..3 & 6, target, resp_mask
    for (int idx = lane; idx < TPW*TSTEPS; idx += 32) {
        int s = idx / TSTEPS;
        int t = idx - s*TSTEPS;
        size_t b = (size_t)(tb + s);
        bool resp = (t >= 20) && (t < 35);
        bool stm  = (t >= 10) && (t < 15);
        int sv = (stimP >> (2*s)) & 3;
        bool irw = (isRewM >> s) & 1;
        float* ub = out + OFFU + b*(TSTEPS*7) + (size_t)t*7;
        ub[0] = (stm && sv == 0) ? 1.0f : 0.0f;
        ub[1] = (stm && sv == 1) ? 1.0f : 0.0f;
        ub[2] = (stm && sv == 2) ? 1.0f : 0.0f;
        ub[3] = (stm && sv == 3) ? 1.0f : 0.0f;
        ub[6] = resp ? 1.0f : 0.0f;
        out[OFFT  + b*TSTEPS + t] = (irw && resp) ? 1.0f : 0.0f;
        out[OFFRS + b*TSTEPS + t] = resp ? 1.0f : 0.0f;
    }
}

extern "C" void kernel_launch(void* const* d_in, const int* in_sizes, int n_in,
                              void* d_out, int out_size) {
    const float* y0     = (const float*)d_in[0];
    const float* noise  = (const float*)d_in[1];
    const int*   stim   = (const int*)  d_in[2];
    const int*   rew    = (const int*)  d_in[3];
    const int*   instr  = (const int*)  d_in[4];
    const float* WinRaw = (const float*)d_in[5];
    const float* Wrec   = (const float*)d_in[6];
    const float* brec   = (const float*)d_in[7];
    const float* wout   = (const float*)d_in[8];
    const float* bout   = (const float*)d_in[9];
    float* out = (float*)d_out;

    const int smem_bytes = SM_FLOATS * (int)sizeof(float);  // ~69.2 KB
    cudaFuncSetAttribute(rnn_dynrouting_kernel,
                         cudaFuncAttributeMaxDynamicSharedMemorySize, smem_bytes);
    rnn_dynrouting_kernel<<<BTOT/TPB, 256, smem_bytes>>>(
        y0, noise, stim, rew, instr, WinRaw, Wrec, brec, wout, bout, out);
}